// round 1
// baseline (speedup 1.0000x reference)
#include <cuda_runtime.h>
#include <cooperative_groups.h>
#include <cstdint>

namespace cg = cooperative_groups;

#define BATCH      8
#define NPTS       65536
#define NSAMP      1024
#define CLUSTER_SZ 8
#define NPC        (NPTS / CLUSTER_SZ)   // 8192 points per CTA
#define NTHREADS   512
#define PPT        (NPC / NTHREADS)      // 16 points per thread
#define PAIRS      (PPT / 2)             // 8 f32x2 pairs
#define NWARPS     (NTHREADS / 32)       // 16

struct CSlot { unsigned long long key; float x, y, z; };

__device__ __forceinline__ unsigned long long pk2(float lo, float hi) {
    unsigned long long r; asm("mov.b64 %0,{%1,%2};" : "=l"(r) : "f"(lo), "f"(hi)); return r;
}
__device__ __forceinline__ void up2(unsigned long long v, float& lo, float& hi) {
    asm("mov.b64 {%0,%1},%2;" : "=f"(lo), "=f"(hi) : "l"(v));
}
__device__ __forceinline__ unsigned long long add2(unsigned long long a, unsigned long long b) {
    unsigned long long r; asm("add.rn.f32x2 %0,%1,%2;" : "=l"(r) : "l"(a), "l"(b)); return r;
}
__device__ __forceinline__ unsigned long long mul2(unsigned long long a, unsigned long long b) {
    unsigned long long r; asm("mul.rn.f32x2 %0,%1,%2;" : "=l"(r) : "l"(a), "l"(b)); return r;
}

extern __shared__ float dynsmem[];

__global__ void __cluster_dims__(CLUSTER_SZ, 1, 1) __launch_bounds__(NTHREADS, 1)
fps_kernel(const float* __restrict__ input, float* __restrict__ out)
{
    cg::cluster_group cluster = cg::this_cluster();
    const unsigned rank = cluster.block_rank();
    const int b    = blockIdx.x / CLUSTER_SZ;
    const int tid  = threadIdx.x;
    const int lane = tid & 31;
    const int warp = tid >> 5;

    // SMEM SoA copy of this CTA's 8192 points (leader coord lookup only)
    float* xs = dynsmem;
    float* ys = xs + NPC;
    float* zs = ys + NPC;

    __shared__ unsigned long long wkey[NWARPS];
    __shared__ CSlot cslots[2][CLUSTER_SZ];   // double-buffered cross-CTA exchange

    const float* pb = input + (size_t)b * NPTS * 3;
    const unsigned g0 = rank * NPC + (unsigned)tid * PPT;   // first global point idx of this thread

    // ---- one-time load: 16 points (48 floats, 16B-aligned) into registers + SMEM SoA ----
    float f[PPT * 3];
    const float4* src = (const float4*)(pb + (size_t)g0 * 3);
    #pragma unroll
    for (int i = 0; i < (PPT * 3) / 4; i++) {
        float4 v = src[i];
        f[4*i] = v.x; f[4*i+1] = v.y; f[4*i+2] = v.z; f[4*i+3] = v.w;
    }
    unsigned long long px[PAIRS], py[PAIRS], pz[PAIRS];
    #pragma unroll
    for (int j = 0; j < PAIRS; j++) {
        px[j] = pk2(f[6*j+0], f[6*j+3]);
        py[j] = pk2(f[6*j+1], f[6*j+4]);
        pz[j] = pk2(f[6*j+2], f[6*j+5]);
    }
    {
        const unsigned l0 = (unsigned)tid * PPT;
        #pragma unroll
        for (int i = 0; i < PPT; i++) {
            xs[l0 + i] = f[3*i]; ys[l0 + i] = f[3*i+1]; zs[l0 + i] = f[3*i+2];
        }
    }

    float md[PPT];
    #pragma unroll
    for (int i = 0; i < PPT; i++) md[i] = 1e10f;   // BIG, matches reference

    // first selection is index 0 (PointNet++ convention)
    float cx = pb[0], cy = pb[1], cz = pb[2];
    if (rank == 0 && tid == 0) {
        out[(size_t)b * NSAMP] = 0.0f;
        float* os = out + BATCH * NSAMP + (size_t)b * NSAMP * 3;
        os[0] = cx; os[1] = cy; os[2] = cz;
    }

    for (int k = 1; k < NSAMP; k++) {
        // ---- distance update (non-contracted: sub, mul, add — matches XLA rounding) ----
        const unsigned long long ncx = pk2(-cx, -cx), ncy = pk2(-cy, -cy), ncz = pk2(-cz, -cz);
        #pragma unroll
        for (int j = 0; j < PAIRS; j++) {
            unsigned long long dx = add2(px[j], ncx);
            unsigned long long dy = add2(py[j], ncy);
            unsigned long long dz = add2(pz[j], ncz);
            unsigned long long s  = add2(add2(mul2(dx, dx), mul2(dy, dy)), mul2(dz, dz));
            float lo, hi; up2(s, lo, hi);
            md[2*j]   = fminf(md[2*j],   lo);
            md[2*j+1] = fminf(md[2*j+1], hi);
        }

        // ---- thread-local argmax (ascending, strict > -> first-occurrence tie break) ----
        float bd = md[0]; unsigned bi = 0;
        #pragma unroll
        for (int i = 1; i < PPT; i++) if (md[i] > bd) { bd = md[i]; bi = (unsigned)i; }
        // packed key: dist bits (nonneg float => uint order) | inverted global index
        unsigned long long key =
            ((unsigned long long)__float_as_uint(bd) << 32) |
            (unsigned long long)(0xFFFFFFFFu - (g0 + bi));

        // ---- warp max ----
        #pragma unroll
        for (int m = 16; m; m >>= 1) {
            unsigned long long o = __shfl_xor_sync(0xFFFFFFFFu, key, m);
            if (o > key) key = o;
        }
        if (lane == 0) wkey[warp] = key;
        __syncthreads();

        // ---- CTA max (warp 0) + leader pushes {key, coords} to all 8 CTAs ----
        if (tid < 32) {
            unsigned long long kk = (lane < NWARPS) ? wkey[lane] : 0ULL;
            #pragma unroll
            for (int m = 16; m; m >>= 1) {
                unsigned long long o = __shfl_xor_sync(0xFFFFFFFFu, kk, m);
                if (o > kk) kk = o;
            }
            if (lane == 0) {
                unsigned gi = 0xFFFFFFFFu - (unsigned)(kk & 0xFFFFFFFFull);
                unsigned li = gi - rank * NPC;      // CTA winner is always local
                float sx = xs[li], sy = ys[li], sz = zs[li];
                const int p = k & 1;
                #pragma unroll
                for (int r = 0; r < CLUSTER_SZ; r++) {
                    CSlot* rp = cluster.map_shared_rank(&cslots[p][rank], r);
                    rp->key = kk; rp->x = sx; rp->y = sy; rp->z = sz;
                }
            }
        }
        cluster.sync();   // orders DSMEM stores, releases slots to all CTAs

        // ---- every thread resolves the cluster winner from local slots ----
        const int p = k & 1;
        unsigned long long bk = cslots[p][0].key; int bs = 0;
        #pragma unroll
        for (int r = 1; r < CLUSTER_SZ; r++) {
            unsigned long long t = cslots[p][r].key;
            if (t > bk) { bk = t; bs = r; }
        }
        cx = cslots[p][bs].x; cy = cslots[p][bs].y; cz = cslots[p][bs].z;

        if (rank == 0 && tid == 0) {
            unsigned widx = 0xFFFFFFFFu - (unsigned)(bk & 0xFFFFFFFFull);
            out[(size_t)b * NSAMP + k] = (float)widx;
            float* os = out + BATCH * NSAMP + ((size_t)b * NSAMP + k) * 3;
            os[0] = cx; os[1] = cy; os[2] = cz;
        }
    }
}

extern "C" void kernel_launch(void* const* d_in, const int* in_sizes, int n_in,
                              void* d_out, int out_size)
{
    const float* input = (const float*)d_in[0];
    float* out = (float*)d_out;

    // 3 * 8192 * 4 = 98304 bytes dynamic SMEM for the SoA point copy
    cudaFuncSetAttribute(fps_kernel, cudaFuncAttributeMaxDynamicSharedMemorySize, 98304);

    fps_kernel<<<BATCH * CLUSTER_SZ, NTHREADS, 98304>>>(input, out);
}